// round 1
// baseline (speedup 1.0000x reference)
#include <cuda_runtime.h>

// CSPN 3x3 propagation:
// out[b,y,x] = sum_{t=0..8, t!=4} kernel[b,t,y,x] * input[b, y+t/3-1, x+t%3-1]  (zero pad)
//            + kernel[b,4,y,x]   * input0[b,y,x]
//
// Shapes: BS=16, H=352, W=1216, all float32.
// HBM-bound: kernel tensor (246.5 MB) streams once; goal is peak bandwidth.

#define BS 16
#define H  352
#define W  1216
#define W4 (W / 4)   // 304

__global__ __launch_bounds__(256) void cspn_kernel(
    const float4* __restrict__ ker4,    // [BS, 9, H, W4]
    const float*  __restrict__ inp,     // [BS, H, W]
    const float4* __restrict__ inp0_4,  // [BS, H, W4]
    float4*       __restrict__ out4)    // [BS, H, W4]
{
    int tid = blockIdx.x * blockDim.x + threadIdx.x;
    const int total = BS * H * W4;
    if (tid >= total) return;

    int x4 = tid % W4;
    int y  = (tid / W4) % H;
    int b  = tid / (W4 * H);
    int x0 = x4 * 4;

    // Gather the 3x6 input neighborhood (rows y-1..y+1, cols x0-1..x0+4),
    // zero-padded at image borders. Neighboring threads' windows overlap
    // heavily -> served from L1/L2 after the first touch.
    float r[3][6];
#pragma unroll
    for (int dy = 0; dy < 3; dy++) {
        int yy = y + dy - 1;
        bool vy = (yy >= 0) && (yy < H);
        const float* row = inp + ((size_t)b * H + (vy ? yy : 0)) * W;
#pragma unroll
        for (int k = 0; k < 6; k++) {
            int xx = x0 + k - 1;
            bool vx = (xx >= 0) && (xx < W);
            r[dy][k] = (vy && vx) ? __ldg(row + xx) : 0.0f;
        }
    }

    const size_t ker_plane = (size_t)H * W4;          // one [H,W4] plane of float4
    const size_t ker_base  = (size_t)b * 9 * ker_plane + (size_t)y * W4 + x4;
    const size_t pix_base  = ((size_t)b * H + y) * W4 + x4;

    float4 acc = make_float4(0.f, 0.f, 0.f, 0.f);

    // 8 neighbor taps (t != 4)
#pragma unroll
    for (int t = 0; t < 9; t++) {
        if (t == 4) continue;
        float4 k4 = __ldg(&ker4[ker_base + (size_t)t * ker_plane]);
        int dy = t / 3;
        int dx = t % 3;
        acc.x = fmaf(k4.x, r[dy][dx + 0], acc.x);
        acc.y = fmaf(k4.y, r[dy][dx + 1], acc.y);
        acc.z = fmaf(k4.z, r[dy][dx + 2], acc.z);
        acc.w = fmaf(k4.w, r[dy][dx + 3], acc.w);
    }

    // Center tap: input0 replaces the im2col center
    {
        float4 k4 = __ldg(&ker4[ker_base + (size_t)4 * ker_plane]);
        float4 c  = __ldg(&inp0_4[pix_base]);
        acc.x = fmaf(k4.x, c.x, acc.x);
        acc.y = fmaf(k4.y, c.y, acc.y);
        acc.z = fmaf(k4.z, c.z, acc.z);
        acc.w = fmaf(k4.w, c.w, acc.w);
    }

    out4[pix_base] = acc;
}

extern "C" void kernel_launch(void* const* d_in, const int* in_sizes, int n_in,
                              void* d_out, int out_size)
{
    const float4* ker4   = (const float4*)d_in[0];  // kernel [16,9,352,1216]
    const float*  inp    = (const float*) d_in[1];  // input  [16,1,352,1216]
    const float4* inp0_4 = (const float4*)d_in[2];  // input0 [16,1,352,1216]
    float4*       out4   = (float4*)d_out;

    const int total   = BS * H * W4;        // 1,712,128 threads
    const int threads = 256;
    const int blocks  = (total + threads - 1) / threads;
    cspn_kernel<<<blocks, threads>>>(ker4, inp, inp0_4, out4);
}

// round 2
// speedup vs baseline: 1.1285x; 1.1285x over previous
#include <cuda_runtime.h>

// CSPN 3x3 propagation (BS=16, H=352, W=1216, f32):
// out[b,y,x] = sum_{t!=4} kernel[b,t,y,x] * input_pad[b, y+t/3-1, x+t%3-1]
//            + kernel[b,4,y,x] * input0[b,y,x]
//
// HBM-bound. Kernel tensor (246.5 MB) is stream-once -> __ldcs (evict-first)
// so L2 is preserved for the 9x-reused input rows. Input gathered as three
// aligned float4 loads per row instead of 6 scalar loads.

#define BS 16
#define H  352
#define W  1216
#define W4 (W / 4)   // 304

__global__ __launch_bounds__(256) void cspn_kernel(
    const float4* __restrict__ ker4,    // [BS, 9, H, W4]
    const float4* __restrict__ inp4,    // [BS, H, W4]
    const float4* __restrict__ inp0_4,  // [BS, H, W4]
    float4*       __restrict__ out4)    // [BS, H, W4]
{
    int tid = blockIdx.x * blockDim.x + threadIdx.x;
    const int total = BS * H * W4;
    if (tid >= total) return;

    int x4 = tid % W4;
    int y  = (tid / W4) % H;
    int b  = tid / (W4 * H);

    const float4 z = make_float4(0.f, 0.f, 0.f, 0.f);

    // 3x6 input window as 3 aligned float4 loads per row.
    // Only left.w and right.x are consumed from the edge vectors, which
    // correspond exactly to columns x0-1 and x0+4 (zero at image borders).
    float r[3][6];
#pragma unroll
    for (int dy = 0; dy < 3; dy++) {
        int yy = y + dy - 1;
        bool vy = (yy >= 0) && (yy < H);
        const float4* rp = inp4 + ((size_t)b * H + (vy ? yy : 0)) * W4;
        float4 lft = (vy && x4 > 0)      ? __ldg(rp + x4 - 1) : z;
        float4 mid =  vy                 ? __ldg(rp + x4)     : z;
        float4 rgt = (vy && x4 < W4 - 1) ? __ldg(rp + x4 + 1) : z;
        r[dy][0] = lft.w;
        r[dy][1] = mid.x;  r[dy][2] = mid.y;
        r[dy][3] = mid.z;  r[dy][4] = mid.w;
        r[dy][5] = rgt.x;
    }

    const size_t ker_plane = (size_t)H * W4;
    const size_t ker_base  = (size_t)b * 9 * ker_plane + (size_t)y * W4 + x4;
    const size_t pix_base  = ((size_t)b * H + y) * W4 + x4;

    float4 acc = z;

    // 8 neighbor taps (kernel tensor: stream-once -> evict-first)
#pragma unroll
    for (int t = 0; t < 9; t++) {
        if (t == 4) continue;
        float4 k4 = __ldcs(&ker4[ker_base + (size_t)t * ker_plane]);
        int dy = t / 3;
        int dx = t % 3;
        acc.x = fmaf(k4.x, r[dy][dx + 0], acc.x);
        acc.y = fmaf(k4.y, r[dy][dx + 1], acc.y);
        acc.z = fmaf(k4.z, r[dy][dx + 2], acc.z);
        acc.w = fmaf(k4.w, r[dy][dx + 3], acc.w);
    }

    // Center tap: input0 replaces the im2col center
    {
        float4 k4 = __ldcs(&ker4[ker_base + (size_t)4 * ker_plane]);
        float4 c  = __ldg(&inp0_4[pix_base]);
        acc.x = fmaf(k4.x, c.x, acc.x);
        acc.y = fmaf(k4.y, c.y, acc.y);
        acc.z = fmaf(k4.z, c.z, acc.z);
        acc.w = fmaf(k4.w, c.w, acc.w);
    }

    __stcs(&out4[pix_base], acc);
}

extern "C" void kernel_launch(void* const* d_in, const int* in_sizes, int n_in,
                              void* d_out, int out_size)
{
    const float4* ker4   = (const float4*)d_in[0];
    const float4* inp4   = (const float4*)d_in[1];
    const float4* inp0_4 = (const float4*)d_in[2];
    float4*       out4   = (float4*)d_out;

    const int total   = BS * H * W4;
    const int threads = 256;
    const int blocks  = (total + threads - 1) / threads;
    cspn_kernel<<<blocks, threads>>>(ker4, inp4, inp0_4, out4);
}